// round 9
// baseline (speedup 1.0000x reference)
#include <cuda_runtime.h>
#include <cuda_fp16.h>
#include <cstdint>

// Problem constants
#define NN   2048
#define BB   64
#define CC   64
#define ED   10
#define BC   4096
#define KCH  3

// ---------------- scratch ----------------------------------------------------
__device__ __half g_Ah  [(size_t)NN * NN];   // softmax(relu(E E^T)), fp16
__device__ __half g_xTTh[(size_t)BC * NN];   // xTT[b*64+c][n] = x[b][n][c], fp16
__device__ float  g_Xg1 [(size_t)NN * BC];   // A @ xT (fp32, for final01)
__device__ __half g_Xg1T[(size_t)BC * NN];   // Xg1^T fp16 (fused in GEMM1 epilogue)
__device__ float  g_Xg2p[(size_t)NN * BC];   // 2 A @ Xg1
__device__ float  g_W   [(size_t)NN * KCH * CC * CC]; // slot0 = W0 - W2 (folded)

// ---------------- helpers ------------------------------------------------
__device__ __forceinline__ uint32_t smem_u32(const void* p) {
    uint32_t a;
    asm("{ .reg .u64 t; cvta.to.shared.u64 t, %1; cvt.u32.u64 %0, t; }" : "=r"(a) : "l"(p));
    return a;
}
__device__ __forceinline__ void cp16(uint32_t dst, const void* src) {
    asm volatile("cp.async.cg.shared.global [%0], [%1], 16;" :: "r"(dst), "l"(src) : "memory");
}
__device__ __forceinline__ void mma16(float* d, const uint32_t* a, const uint32_t* b) {
    asm volatile("mma.sync.aligned.m16n8k16.row.col.f32.f16.f16.f32 "
        "{%0,%1,%2,%3}, {%4,%5,%6,%7}, {%8,%9}, {%0,%1,%2,%3};"
        : "+f"(d[0]), "+f"(d[1]), "+f"(d[2]), "+f"(d[3])
        : "r"(a[0]), "r"(a[1]), "r"(a[2]), "r"(a[3]), "r"(b[0]), "r"(b[1]));
}
__device__ __forceinline__ void ldmat4(uint32_t* r, uint32_t addr) {
    asm volatile("ldmatrix.sync.aligned.m8n8.x4.shared.b16 {%0,%1,%2,%3}, [%4];"
        : "=r"(r[0]), "=r"(r[1]), "=r"(r[2]), "=r"(r[3]) : "r"(addr));
}

// ---------------- fp16 mma.sync GEMM: C = alpha * Aop @ Bop^T ---------------
// CTA tile 128x128, warp tile 64x32, K-chunk 64, 3-stage cp.async pipeline,
// single __syncthreads per chunk, ldmatrix fragment feeds with kk-level
// register double-buffering (LDSM of kk+1 overlaps MMA of kk).
__global__ __launch_bounds__(256, 2)
void gemm_mma(const __half* __restrict__ Aop, const __half* __restrict__ Bop,
              float* __restrict__ C, int ldcN, float alpha,
              __half* __restrict__ Ct)
{
    extern __shared__ char smem[];
    uint32_t sbase = smem_u32(smem);
    // stage s (32 KB): A at s*32768 (16KB = 128 rows x 128B), B at +16384

    int tid = threadIdx.x, wid = tid >> 5, lid = tid & 31;
    int m0 = blockIdx.y * 128, n0 = blockIdx.x * 128;

    // ---- loader mapping ----
    int ldr = tid >> 3, ldc8 = tid & 7;
    uint32_t swz_ld = (uint32_t)(ldr * 128 + ((ldc8 * 16) ^ ((ldr & 7) * 16)));
    const __half* ga = Aop + (size_t)(m0 + ldr) * NN + ldc8 * 8;
    const __half* gb = Bop + (size_t)(n0 + ldr) * NN + ldc8 * 8;

#define LOAD_CHUNK(kc, buf) do { \
    int _k0 = (kc) * 64; \
    uint32_t _as = sbase + (uint32_t)(buf) * 32768u + swz_ld; \
    uint32_t _bs = _as + 16384u; \
    _Pragma("unroll") for (int i = 0; i < 4; i++) { \
        cp16(_as + (uint32_t)i * 4096u, ga + (size_t)i * 32 * NN + _k0); \
        cp16(_bs + (uint32_t)i * 4096u, gb + (size_t)i * 32 * NN + _k0); \
    } \
    asm volatile("cp.async.commit_group;" ::: "memory"); \
} while (0)

    // ---- compute mapping (2 x 4 warps of 64x32) ----
    int wm = wid & 1, wn = wid >> 1;
    int lane4 = lid & 3, lgrp = lid >> 2;
    int t7 = lid & 7;
    uint32_t swzmask = (uint32_t)(t7 * 16);

    uint32_t a_rowbase = (uint32_t)((wm * 64 + t7 + (((lid >> 3) & 1) << 3)) * 128);
    uint32_t a_khoff   = (uint32_t)(((lid >> 4) & 1) * 16);
    uint32_t b_rowbase = (uint32_t)((wn * 32 + t7 + (((lid >> 4) & 1) << 3)) * 128);
    uint32_t b_khoff   = (uint32_t)(((lid >> 3) & 1) * 16);

    float acc[4][4][4];
#pragma unroll
    for (int mt = 0; mt < 4; mt++)
#pragma unroll
        for (int nt = 0; nt < 4; nt++)
#pragma unroll
            for (int c = 0; c < 4; c++) acc[mt][nt][c] = 0.f;

    LOAD_CHUNK(0, 0);
    LOAD_CHUNK(1, 1);

    // fragment double buffers
    uint32_t afr[2][4][4], bfr[2][2][4];

#define LDFRAG(pb, ab_, bb_, kk) do { \
    uint32_t _ak = ((uint32_t)((kk) * 32) + a_khoff) ^ swzmask; \
    uint32_t _bk = ((uint32_t)((kk) * 32) + b_khoff) ^ swzmask; \
    _Pragma("unroll") for (int mt = 0; mt < 4; mt++) \
        ldmat4(afr[pb][mt], (ab_) + a_rowbase + (uint32_t)(mt * 2048) + _ak); \
    _Pragma("unroll") for (int np = 0; np < 2; np++) \
        ldmat4(bfr[pb][np], (bb_) + b_rowbase + (uint32_t)(np * 2048) + _bk); \
} while (0)

#define MMAS(pb) do { \
    _Pragma("unroll") for (int mt = 0; mt < 4; mt++) \
        _Pragma("unroll") for (int nt = 0; nt < 4; nt++) \
            mma16(acc[mt][nt], afr[pb][mt], &bfr[pb][nt >> 1][(nt & 1) * 2]); \
} while (0)

    int buf = 0, nbuf = 2;
    for (int kc = 0; kc < 32; kc++) {
        asm volatile("cp.async.wait_group 1;" ::: "memory");
        __syncthreads();

        if (kc + 2 < 32) LOAD_CHUNK(kc + 2, nbuf);
        else asm volatile("cp.async.commit_group;" ::: "memory");

        uint32_t ab = sbase + (uint32_t)buf * 32768u;
        uint32_t bb = ab + 16384u;

        // kk-level software pipeline: LDSM(kk+1) overlaps MMA(kk)
        LDFRAG(0, ab, bb, 0);
        LDFRAG(1, ab, bb, 1);
        MMAS(0);
        LDFRAG(0, ab, bb, 2);
        MMAS(1);
        LDFRAG(1, ab, bb, 3);
        MMAS(0);
        MMAS(1);

        int t = buf; buf = (buf == 2) ? 0 : buf + 1; nbuf = t;
    }
#undef LOAD_CHUNK
#undef LDFRAG
#undef MMAS

    // ---- epilogue ----
    __syncthreads();
    float* st = (float*)smem;  // 128 x 128 staging, stride 129

    int row0 = m0 + wm * 64;
    int col0 = n0 + wn * 32 + lane4 * 2;
    int lr0  = wm * 64;
    int lc0  = wn * 32 + lane4 * 2;
#pragma unroll
    for (int mt = 0; mt < 4; mt++) {
#pragma unroll
        for (int nt = 0; nt < 4; nt++) {
            int r = row0 + mt * 16 + lgrp;
            int c = col0 + nt * 8;
            float v0 = alpha * acc[mt][nt][0];
            float v1 = alpha * acc[mt][nt][1];
            float v2 = alpha * acc[mt][nt][2];
            float v3 = alpha * acc[mt][nt][3];
            *(float2*)&C[(size_t)r * ldcN + c]       = make_float2(v0, v1);
            *(float2*)&C[(size_t)(r + 8) * ldcN + c] = make_float2(v2, v3);
            if (Ct) {
                int lr = lr0 + mt * 16 + lgrp;
                int lc = lc0 + nt * 8;
                st[lr * 129 + lc]           = v0;
                st[lr * 129 + lc + 1]       = v1;
                st[(lr + 8) * 129 + lc]     = v2;
                st[(lr + 8) * 129 + lc + 1] = v3;
            }
        }
    }
    if (Ct) {
        __syncthreads();
        for (int i = tid; i < 16384; i += 256) {
            int c = i >> 7, r = i & 127;
            Ct[(size_t)(n0 + c) * NN + m0 + r] = __float2half_rn(st[r * 129 + c]);
        }
    }
}

// ---------------- A = softmax(relu(E E^T)), fp16 output ---------------------
__global__ __launch_bounds__(256) void supports_kernel(const float* __restrict__ E)
{
    int n = blockIdx.x, tid = threadIdx.x;
    float en[ED];
#pragma unroll
    for (int d = 0; d < ED; d++) en[d] = E[n * ED + d];

    float v[8], mx = 0.0f;
#pragma unroll
    for (int j = 0; j < 8; j++) {
        int m = j * 256 + tid;
        float dot = 0.f;
#pragma unroll
        for (int d = 0; d < ED; d++) dot += en[d] * __ldg(&E[m * ED + d]);
        v[j] = fmaxf(dot, 0.f);
        mx = fmaxf(mx, v[j]);
    }
    __shared__ float red[256];
    red[tid] = mx; __syncthreads();
    for (int s = 128; s > 0; s >>= 1) {
        if (tid < s) red[tid] = fmaxf(red[tid], red[tid + s]);
        __syncthreads();
    }
    mx = red[0]; __syncthreads();
    float sum = 0.f;
#pragma unroll
    for (int j = 0; j < 8; j++) { v[j] = expf(v[j] - mx); sum += v[j]; }
    red[tid] = sum; __syncthreads();
    for (int s = 128; s > 0; s >>= 1) {
        if (tid < s) red[tid] += red[tid + s];
        __syncthreads();
    }
    float inv = 1.0f / red[0];
#pragma unroll
    for (int j = 0; j < 8; j++)
        g_Ah[(size_t)n * NN + j * 256 + tid] = __float2half_rn(v[j] * inv);
}

// ---------------- xTT[b*64+c][n] = x[b][n][c], fp16 --------------------------
__global__ __launch_bounds__(256) void transpose_x_kernel(const float* __restrict__ x)
{
    __shared__ float t[32][33];
    int tx = threadIdx.x, ty = threadIdx.y;
    int b = blockIdx.z;
    int n0 = blockIdx.x * 32, c0 = blockIdx.y * 32;
    const float* S = x + (size_t)b * NN * CC;
#pragma unroll
    for (int i = 0; i < 32; i += 8)
        t[ty + i][tx] = S[(size_t)(n0 + ty + i) * CC + c0 + tx];
    __syncthreads();
    __half* D = g_xTTh + (size_t)b * CC * NN;
#pragma unroll
    for (int i = 0; i < 32; i += 8)
        D[(size_t)(c0 + ty + i) * NN + n0 + tx] = __float2half_rn(t[tx][ty + i]);
}

// ---------------- W: slot0 = sum_d E (Wp0 - Wp2); slot1/2 as-is --------------
__global__ __launch_bounds__(256) void weights_kernel(const float* __restrict__ E,
                                                      const float* __restrict__ Wp)
{
    int t = blockIdx.x * blockDim.x + threadIdx.x;
    int j4 = t % 3072;
    int n  = t / 3072;
    int isK0 = (j4 < 1024);
    float4 acc = make_float4(0.f, 0.f, 0.f, 0.f);
#pragma unroll
    for (int d = 0; d < ED; d++) {
        float  e = __ldg(&E[n * ED + d]);
        float4 w = *(const float4*)&Wp[(size_t)d * 12288 + j4 * 4];
        if (isK0) {
            float4 w2 = *(const float4*)&Wp[(size_t)d * 12288 + (j4 + 2048) * 4];
            w.x -= w2.x; w.y -= w2.y; w.z -= w2.z; w.w -= w2.w;
        }
        acc.x += e * w.x; acc.y += e * w.y; acc.z += e * w.z; acc.w += e * w.w;
    }
    *(float4*)&g_W[(size_t)n * 12288 + j4 * 4] = acc;
}

// ---------------- final01: out[:,n,:] = x@(W0-W2) + Xg1@W1 + bias ------------
__global__ __launch_bounds__(256) void final01_kernel(const float* __restrict__ x,
                                                      const float* __restrict__ E,
                                                      const float* __restrict__ bp,
                                                      float* __restrict__ out)
{
    int n = blockIdx.x, tid = threadIdx.x;
    int tx = tid & 15, ty = tid >> 4;

    __shared__ float Xs[64][64];
    __shared__ float Ws[64][64];

    float acc[4][4];
#pragma unroll
    for (int r = 0; r < 4; r++)
#pragma unroll
        for (int c = 0; c < 4; c++) acc[r][c] = 0.f;

#pragma unroll
    for (int k = 0; k < 2; k++) {
        if (k == 0) {
#pragma unroll
            for (int t = 0; t < 4; t++) {
                int e = tid + t * 256;
                int b = e >> 4, i4 = e & 15;
                *(float4*)&Xs[b][i4 * 4] =
                    *(const float4*)&x[((size_t)b * NN + n) * CC + i4 * 4];
            }
        } else {
            const float* src = g_Xg1 + (size_t)n * BC;
#pragma unroll
            for (int t = 0; t < 4; t++) {
                int e = tid + t * 256;
                ((float4*)Xs)[e] = ((const float4*)src)[e];
            }
        }
        const float* wsrc = g_W + (size_t)n * 12288 + (size_t)k * 4096;
#pragma unroll
        for (int t = 0; t < 4; t++) {
            int e = tid + t * 256;
            ((float4*)Ws)[e] = ((const float4*)wsrc)[e];
        }
        __syncthreads();

#pragma unroll 8
        for (int i = 0; i < 64; i++) {
            float xr[4];
#pragma unroll
            for (int r = 0; r < 4; r++) xr[r] = Xs[ty * 4 + r][i];
            float4 wv = *(const float4*)&Ws[i][tx * 4];
#pragma unroll
            for (int r = 0; r < 4; r++) {
                acc[r][0] += xr[r] * wv.x;
                acc[r][1] += xr[r] * wv.y;
                acc[r][2] += xr[r] * wv.z;
                acc[r][3] += xr[r] * wv.w;
            }
        }
        __syncthreads();
    }

    float bias[4] = {0.f, 0.f, 0.f, 0.f};
#pragma unroll
    for (int d = 0; d < ED; d++) {
        float e = __ldg(&E[n * ED + d]);
#pragma unroll
        for (int c = 0; c < 4; c++) bias[c] += e * __ldg(&bp[d * CC + tx * 4 + c]);
    }

#pragma unroll
    for (int r = 0; r < 4; r++) {
        int b = ty * 4 + r;
        float4 v = make_float4(acc[r][0] + bias[0], acc[r][1] + bias[1],
                               acc[r][2] + bias[2], acc[r][3] + bias[3]);
        *(float4*)&out[((size_t)b * NN + n) * CC + tx * 4] = v;
    }
}

// ---------------- final2: out += Xg2p @ W2 (x-term folded into W0) -----------
__global__ __launch_bounds__(256) void final2_kernel(float* __restrict__ out)
{
    int n = blockIdx.x, tid = threadIdx.x;
    int tx = tid & 15, ty = tid >> 4;

    __shared__ float Xs[64][64];
    __shared__ float Ws[64][64];

    const float* src = g_Xg2p + (size_t)n * BC;
#pragma unroll
    for (int t = 0; t < 4; t++) {
        int e = tid + t * 256;
        ((float4*)Xs)[e] = ((const float4*)src)[e];
    }
    const float* wsrc = g_W + (size_t)n * 12288 + (size_t)2 * 4096;
#pragma unroll
    for (int t = 0; t < 4; t++) {
        int e = tid + t * 256;
        ((float4*)Ws)[e] = ((const float4*)wsrc)[e];
    }
    __syncthreads();

    float acc[4][4];
#pragma unroll
    for (int r = 0; r < 4; r++)
#pragma unroll
        for (int c = 0; c < 4; c++) acc[r][c] = 0.f;

#pragma unroll 8
    for (int i = 0; i < 64; i++) {
        float xr[4];
#pragma unroll
        for (int r = 0; r < 4; r++) xr[r] = Xs[ty * 4 + r][i];
        float4 wv = *(const float4*)&Ws[i][tx * 4];
#pragma unroll
        for (int r = 0; r < 4; r++) {
            acc[r][0] += xr[r] * wv.x;
            acc[r][1] += xr[r] * wv.y;
            acc[r][2] += xr[r] * wv.z;
            acc[r][3] += xr[r] * wv.w;
        }
    }

#pragma unroll
    for (int r = 0; r < 4; r++) {
        int b = ty * 4 + r;
        float4 v = *(float4*)&out[((size_t)b * NN + n) * CC + tx * 4];
        v.x += acc[r][0]; v.y += acc[r][1]; v.z += acc[r][2]; v.w += acc[r][3];
        *(float4*)&out[((size_t)b * NN + n) * CC + tx * 4] = v;
    }
}

// ---------------- launch ----------------------------------------------------
#define GEMM_SMEM 98304

extern "C" void kernel_launch(void* const* d_in, const int* in_sizes, int n_in,
                              void* d_out, int out_size)
{
    const float* x  = (const float*)d_in[0];
    const float* E  = (const float*)d_in[1];
    const float* Wp = (const float*)d_in[2];
    const float* bp = (const float*)d_in[3];
    float* out = (float*)d_out;

    __half *pAh, *pxTTh, *pXg1T;
    float *pXg1, *pXg2p;
    cudaGetSymbolAddress((void**)&pAh,   g_Ah);
    cudaGetSymbolAddress((void**)&pxTTh, g_xTTh);
    cudaGetSymbolAddress((void**)&pXg1,  g_Xg1);
    cudaGetSymbolAddress((void**)&pXg1T, g_Xg1T);
    cudaGetSymbolAddress((void**)&pXg2p, g_Xg2p);

    static bool init_done = false;
    static cudaStream_t s1, s2;
    static cudaEvent_t e0, e1, e2, e3;
    if (!init_done) {
        cudaFuncSetAttribute(gemm_mma, cudaFuncAttributeMaxDynamicSharedMemorySize, GEMM_SMEM);
        cudaStreamCreateWithFlags(&s1, cudaStreamNonBlocking);
        cudaStreamCreateWithFlags(&s2, cudaStreamNonBlocking);
        cudaEventCreateWithFlags(&e0, cudaEventDisableTiming);
        cudaEventCreateWithFlags(&e1, cudaEventDisableTiming);
        cudaEventCreateWithFlags(&e2, cudaEventDisableTiming);
        cudaEventCreateWithFlags(&e3, cudaEventDisableTiming);
        init_done = true;
    }

    // fork side streams from the capture-origin (default) stream
    cudaEventRecord(e0, 0);
    cudaStreamWaitEvent(s1, e0, 0);
    cudaStreamWaitEvent(s2, e0, 0);

    // s1: x transpose (fp16)          — needed by GEMM1
    transpose_x_kernel<<<dim3(64, 2, 64), dim3(32, 8), 0, s1>>>(x);
    // s2: per-node weights (fold)     — needed by finals
    weights_kernel<<<(NN * 3072) / 256, 256, 0, s2>>>(E, Wp);
    // main: adjacency (fp16)          — needed by GEMM1
    supports_kernel<<<NN, 256>>>(E);

    // join s1 before GEMM1
    cudaEventRecord(e1, s1);
    cudaStreamWaitEvent(0, e1, 0);

    // GEMM1: Xg1 = A @ xT  (+ fused fp16 transposed copy Xg1T)
    gemm_mma<<<dim3(BC / 128, NN / 128), 256, GEMM_SMEM>>>(pAh, pxTTh, pXg1, BC, 1.0f, pXg1T);

    // final01 on s2 (needs Xg1 + W): overlaps GEMM2
    cudaEventRecord(e2, 0);
    cudaStreamWaitEvent(s2, e2, 0);
    final01_kernel<<<NN, 256, 0, s2>>>(x, E, bp, out);

    // GEMM2 on main: Xg2p = 2 A @ Xg1
    gemm_mma<<<dim3(BC / 128, NN / 128), 256, GEMM_SMEM>>>(pAh, pXg1T, pXg2p, BC, 2.0f, nullptr);

    // join s2, then final accumulation
    cudaEventRecord(e3, s2);
    cudaStreamWaitEvent(0, e3, 0);
    final2_kernel<<<NN, 256>>>(out);
}

// round 10
// speedup vs baseline: 1.3079x; 1.3079x over previous
#include <cuda_runtime.h>
#include <cuda_fp16.h>
#include <cstdint>

// Problem constants
#define NN   2048
#define BB   64
#define CC   64
#define ED   10
#define BC   4096
#define KCH  3

// ---------------- scratch (all fp16 except none) ------------------------------
__device__ __half g_Ah   [(size_t)NN * NN];   // softmax(relu(E E^T)), fp16
__device__ __half g_xTTh [(size_t)BC * NN];   // xTT[b*64+c][n], fp16 (GEMM1 B operand)
__device__ __half g_xh   [(size_t)NN * BC];   // x as [n][b*64+c], fp16 (final_tc seg0)
__device__ __half g_Xg1h [(size_t)NN * BC];   // A @ xT, fp16 [n][bc]
__device__ __half g_Xg1T [(size_t)BC * NN];   // Xg1^T fp16 (GEMM2 B operand)
__device__ __half g_Xg2ph[(size_t)NN * BC];   // 2 A @ Xg1, fp16 [n][bc]
__device__ __half g_Wph  [(size_t)ED * KCH * CC * CC]; // Wp pre-transposed [d][k][o][i], slot0 folded
__device__ __half g_WhT  [(size_t)NN * KCH * CC * CC]; // per-node W^T [n][k][o][i]

// ---------------- helpers ------------------------------------------------
__device__ __forceinline__ uint32_t smem_u32(const void* p) {
    uint32_t a;
    asm("{ .reg .u64 t; cvta.to.shared.u64 t, %1; cvt.u32.u64 %0, t; }" : "=r"(a) : "l"(p));
    return a;
}
__device__ __forceinline__ void cp16(uint32_t dst, const void* src) {
    asm volatile("cp.async.cg.shared.global [%0], [%1], 16;" :: "r"(dst), "l"(src) : "memory");
}
__device__ __forceinline__ void mma16(float* d, const uint32_t* a, const uint32_t* b) {
    asm volatile("mma.sync.aligned.m16n8k16.row.col.f32.f16.f16.f32 "
        "{%0,%1,%2,%3}, {%4,%5,%6,%7}, {%8,%9}, {%0,%1,%2,%3};"
        : "+f"(d[0]), "+f"(d[1]), "+f"(d[2]), "+f"(d[3])
        : "r"(a[0]), "r"(a[1]), "r"(a[2]), "r"(a[3]), "r"(b[0]), "r"(b[1]));
}
__device__ __forceinline__ void ldmat4(uint32_t* r, uint32_t addr) {
    asm volatile("ldmatrix.sync.aligned.m8n8.x4.shared.b16 {%0,%1,%2,%3}, [%4];"
        : "=r"(r[0]), "=r"(r[1]), "=r"(r[2]), "=r"(r[3]) : "r"(addr));
}

// ---------------- fp16 mma.sync GEMM: Ch = fp16(alpha * Aop @ Bop^T) ---------
// CTA tile 128x128, warp tile 64x32, K-chunk 64, 3-stage cp.async pipeline.
// If Ct != null, also writes fp16 transposed tile to Ct (ld = NN).
__global__ __launch_bounds__(256, 2)
void gemm_mma(const __half* __restrict__ Aop, const __half* __restrict__ Bop,
              __half* __restrict__ Ch, int ldcN, float alpha,
              __half* __restrict__ Ct)
{
    extern __shared__ char smem[];
    uint32_t sbase = smem_u32(smem);

    int tid = threadIdx.x, wid = tid >> 5, lid = tid & 31;
    int m0 = blockIdx.y * 128, n0 = blockIdx.x * 128;

    int ldr = tid >> 3, ldc8 = tid & 7;
    uint32_t swz_ld = (uint32_t)(ldr * 128 + ((ldc8 * 16) ^ ((ldr & 7) * 16)));
    const __half* ga = Aop + (size_t)(m0 + ldr) * NN + ldc8 * 8;
    const __half* gb = Bop + (size_t)(n0 + ldr) * NN + ldc8 * 8;

#define LOAD_CHUNK(kc, buf) do { \
    int _k0 = (kc) * 64; \
    uint32_t _as = sbase + (uint32_t)(buf) * 32768u + swz_ld; \
    uint32_t _bs = _as + 16384u; \
    _Pragma("unroll") for (int i = 0; i < 4; i++) { \
        cp16(_as + (uint32_t)i * 4096u, ga + (size_t)i * 32 * NN + _k0); \
        cp16(_bs + (uint32_t)i * 4096u, gb + (size_t)i * 32 * NN + _k0); \
    } \
    asm volatile("cp.async.commit_group;" ::: "memory"); \
} while (0)

    int wm = wid & 1, wn = wid >> 1;
    int lane4 = lid & 3, lgrp = lid >> 2;
    int t7 = lid & 7;
    uint32_t swzmask = (uint32_t)(t7 * 16);

    uint32_t a_rowbase = (uint32_t)((wm * 64 + t7 + (((lid >> 3) & 1) << 3)) * 128);
    uint32_t a_khoff   = (uint32_t)(((lid >> 4) & 1) * 16);
    uint32_t b_rowbase = (uint32_t)((wn * 32 + t7 + (((lid >> 4) & 1) << 3)) * 128);
    uint32_t b_khoff   = (uint32_t)(((lid >> 3) & 1) * 16);

    float acc[4][4][4];
#pragma unroll
    for (int mt = 0; mt < 4; mt++)
#pragma unroll
        for (int nt = 0; nt < 4; nt++)
#pragma unroll
            for (int c = 0; c < 4; c++) acc[mt][nt][c] = 0.f;

    LOAD_CHUNK(0, 0);
    LOAD_CHUNK(1, 1);

    int buf = 0, nbuf = 2;
    for (int kc = 0; kc < 32; kc++) {
        asm volatile("cp.async.wait_group 1;" ::: "memory");
        __syncthreads();

        if (kc + 2 < 32) LOAD_CHUNK(kc + 2, nbuf);
        else asm volatile("cp.async.commit_group;" ::: "memory");

        uint32_t ab = sbase + (uint32_t)buf * 32768u;
        uint32_t bb = ab + 16384u;
#pragma unroll
        for (int kk = 0; kk < 4; kk++) {
            uint32_t a[4][4], bfr[2][4];
            uint32_t a_k = ((uint32_t)(kk * 32) + a_khoff) ^ swzmask;
            uint32_t b_k = ((uint32_t)(kk * 32) + b_khoff) ^ swzmask;
#pragma unroll
            for (int mt = 0; mt < 4; mt++)
                ldmat4(a[mt], ab + a_rowbase + (uint32_t)(mt * 2048) + a_k);
#pragma unroll
            for (int np = 0; np < 2; np++)
                ldmat4(bfr[np], bb + b_rowbase + (uint32_t)(np * 2048) + b_k);
#pragma unroll
            for (int mt = 0; mt < 4; mt++)
#pragma unroll
                for (int nt = 0; nt < 4; nt++)
                    mma16(acc[mt][nt], a[mt], &bfr[nt >> 1][(nt & 1) * 2]);
        }
        int t = buf; buf = (buf == 2) ? 0 : buf + 1; nbuf = t;
    }
#undef LOAD_CHUNK

    // ---- epilogue ----
    __syncthreads();
    float* st = (float*)smem;  // 128 x 128 staging, stride 129

    int row0 = m0 + wm * 64;
    int col0 = n0 + wn * 32 + lane4 * 2;
    int lr0  = wm * 64;
    int lc0  = wn * 32 + lane4 * 2;
#pragma unroll
    for (int mt = 0; mt < 4; mt++) {
#pragma unroll
        for (int nt = 0; nt < 4; nt++) {
            int r = row0 + mt * 16 + lgrp;
            int c = col0 + nt * 8;
            float v0 = alpha * acc[mt][nt][0];
            float v1 = alpha * acc[mt][nt][1];
            float v2 = alpha * acc[mt][nt][2];
            float v3 = alpha * acc[mt][nt][3];
            *(__half2*)&Ch[(size_t)r * ldcN + c]       = __floats2half2_rn(v0, v1);
            *(__half2*)&Ch[(size_t)(r + 8) * ldcN + c] = __floats2half2_rn(v2, v3);
            if (Ct) {
                int lr = lr0 + mt * 16 + lgrp;
                int lc = lc0 + nt * 8;
                st[lr * 129 + lc]           = v0;
                st[lr * 129 + lc + 1]       = v1;
                st[(lr + 8) * 129 + lc]     = v2;
                st[(lr + 8) * 129 + lc + 1] = v3;
            }
        }
    }
    if (Ct) {
        __syncthreads();
        for (int i = tid; i < 16384; i += 256) {
            int c = i >> 7, r = i & 127;
            Ct[(size_t)(n0 + c) * NN + m0 + r] = __float2half_rn(st[r * 129 + c]);
        }
    }
}

// ---------------- A = softmax(relu(E E^T)), fp16 output ---------------------
__global__ __launch_bounds__(256) void supports_kernel(const float* __restrict__ E)
{
    int n = blockIdx.x, tid = threadIdx.x;
    float en[ED];
#pragma unroll
    for (int d = 0; d < ED; d++) en[d] = E[n * ED + d];

    float v[8], mx = 0.0f;
#pragma unroll
    for (int j = 0; j < 8; j++) {
        int m = j * 256 + tid;
        float dot = 0.f;
#pragma unroll
        for (int d = 0; d < ED; d++) dot += en[d] * __ldg(&E[m * ED + d]);
        v[j] = fmaxf(dot, 0.f);
        mx = fmaxf(mx, v[j]);
    }
    __shared__ float red[256];
    red[tid] = mx; __syncthreads();
    for (int s = 128; s > 0; s >>= 1) {
        if (tid < s) red[tid] = fmaxf(red[tid], red[tid + s]);
        __syncthreads();
    }
    mx = red[0]; __syncthreads();
    float sum = 0.f;
#pragma unroll
    for (int j = 0; j < 8; j++) { v[j] = expf(v[j] - mx); sum += v[j]; }
    red[tid] = sum; __syncthreads();
    for (int s = 128; s > 0; s >>= 1) {
        if (tid < s) red[tid] += red[tid + s];
        __syncthreads();
    }
    float inv = 1.0f / red[0];
#pragma unroll
    for (int j = 0; j < 8; j++)
        g_Ah[(size_t)n * NN + j * 256 + tid] = __float2half_rn(v[j] * inv);
}

// ---------------- x transposes: xTTh [bc][n] + xh [n][bc], both fp16 ---------
__global__ __launch_bounds__(256) void transpose_x_kernel(const float* __restrict__ x)
{
    __shared__ float t[32][33];
    int tx = threadIdx.x, ty = threadIdx.y;
    int b = blockIdx.z;
    int n0 = blockIdx.x * 32, c0 = blockIdx.y * 32;
    const float* S = x + (size_t)b * NN * CC;
#pragma unroll
    for (int i = 0; i < 32; i += 8) {
        float v = S[(size_t)(n0 + ty + i) * CC + c0 + tx];
        t[ty + i][tx] = v;
        g_xh[(size_t)(n0 + ty + i) * BC + b * CC + c0 + tx] = __float2half_rn(v);
    }
    __syncthreads();
    __half* D = g_xTTh + (size_t)b * CC * NN;
#pragma unroll
    for (int i = 0; i < 32; i += 8)
        D[(size_t)(c0 + ty + i) * NN + n0 + tx] = __float2half_rn(t[tx][ty + i]);
}

// ---------------- prepW: Wph[d][k][o][i] = fp16(Wp[d][k][i][o] - (k==0)*Wp[d][2][i][o])
__global__ __launch_bounds__(256) void prepW_kernel(const float* __restrict__ Wp)
{
    int t = blockIdx.x * 256 + threadIdx.x;     // 122880 elements
    int i  = t & 63;
    int o  = (t >> 6) & 63;
    int kd = t >> 12;                            // d*3 + k
    int k  = kd % 3, d = kd / 3;
    float v = Wp[((size_t)kd * 64 + i) * 64 + o];
    if (k == 0) v -= Wp[((size_t)(d * 3 + 2) * 64 + i) * 64 + o];
    g_Wph[t] = __float2half_rn(v);
}

// ---------------- weights: WhT[n][k][o][i] = sum_d E[n,d] Wph[d][k][o][i] ----
__global__ __launch_bounds__(256) void weights_kernel(const float* __restrict__ E)
{
    size_t t = (size_t)blockIdx.x * 256 + threadIdx.x;  // 2048*1536
    int j8 = (int)(t % 1536);       // 8-half (16B) group within node
    int n  = (int)(t / 1536);

    float acc[8];
#pragma unroll
    for (int q = 0; q < 8; q++) acc[q] = 0.f;

#pragma unroll
    for (int d = 0; d < ED; d++) {
        float e = __ldg(&E[n * ED + d]);
        uint4 w = *(const uint4*)&g_Wph[(size_t)d * 12288 + (size_t)j8 * 8];
        const __half2* h = (const __half2*)&w;
#pragma unroll
        for (int q = 0; q < 4; q++) {
            float2 f = __half22float2(h[q]);
            acc[q * 2]     += e * f.x;
            acc[q * 2 + 1] += e * f.y;
        }
    }
    uint4 outw;
    __half2* ho = (__half2*)&outw;
#pragma unroll
    for (int q = 0; q < 4; q++)
        ho[q] = __floats2half2_rn(acc[q * 2], acc[q * 2 + 1]);
    *(uint4*)&g_WhT[(size_t)n * 12288 + (size_t)j8 * 8] = outw;
}

// ---------------- final_tc: out[:,n,:] = [x|Xg1|Xg2p] @ WhT_n + bias ---------
// One block per node, 128 threads (4 warps), tensor-core m16n8k16.
// Smem: 3 Xg tiles (64b x 64c fp16, 8KB each) + 3 Wt tiles (64o x 64i) + bias.
#define FT_SMEM (49152 + 256)
__global__ __launch_bounds__(128)
void final_tc(const float* __restrict__ E, const float* __restrict__ bp,
              float* __restrict__ out)
{
    extern __shared__ char sm[];
    uint32_t sb = smem_u32(sm);
    float* biass = (float*)(sm + 49152);
    int n = blockIdx.x, tid = threadIdx.x, wid = tid >> 5, lid = tid & 31;

    // bias[o] = sum_d E[n,d] * bp[d][o]
    if (tid < 64) {
        float b = 0.f;
#pragma unroll
        for (int d = 0; d < ED; d++) b += __ldg(&E[n * ED + d]) * __ldg(&bp[d * CC + tid]);
        biass[tid] = b;
    }

    // load Xg segments (x, Xg1, Xg2p), each 64 rows x 128B, swizzled
    const __half* srcs[3] = { g_xh   + (size_t)n * BC,
                              g_Xg1h + (size_t)n * BC,
                              g_Xg2ph+ (size_t)n * BC };
#pragma unroll
    for (int s = 0; s < 3; s++) {
        const char* g = (const char*)srcs[s];
        for (int ch = tid; ch < 512; ch += 128) {
            int r = ch >> 3, c16 = ch & 7;
            uint32_t dst = sb + (uint32_t)(s * 8192)
                         + (uint32_t)(r * 128 + ((c16 * 16) ^ ((r & 7) * 16)));
            cp16(dst, g + r * 128 + c16 * 16);
        }
    }
    // load WhT: 192 rows (k*64+o) x 128B, contiguous, swizzled per row
    {
        const char* g = (const char*)(g_WhT + (size_t)n * 12288);
        for (int ch = tid; ch < 1536; ch += 128) {
            int r = ch >> 3, c16 = ch & 7;
            uint32_t dst = sb + 24576u
                         + (uint32_t)(r * 128 + ((c16 * 16) ^ ((r & 7) * 16)));
            cp16(dst, g + r * 128 + c16 * 16);
        }
    }
    asm volatile("cp.async.commit_group;" ::: "memory");
    asm volatile("cp.async.wait_group 0;" ::: "memory");
    __syncthreads();

    int t7 = lid & 7, lane4 = lid & 3, lgrp = lid >> 2;
    uint32_t swzmask = (uint32_t)(t7 * 16);
    uint32_t a_rowbase = (uint32_t)((wid * 16 + t7 + (((lid >> 3) & 1) << 3)) * 128);
    uint32_t a_khoff   = (uint32_t)(((lid >> 4) & 1) * 16);
    uint32_t b_rowbase = (uint32_t)((t7 + (((lid >> 4) & 1) << 3)) * 128);
    uint32_t b_khoff   = (uint32_t)(((lid >> 3) & 1) * 16);

    float acc[8][4];
#pragma unroll
    for (int j = 0; j < 8; j++)
#pragma unroll
        for (int c = 0; c < 4; c++) acc[j][c] = 0.f;

#pragma unroll
    for (int s = 0; s < 3; s++) {
#pragma unroll
        for (int kk = 0; kk < 4; kk++) {
            uint32_t a[4], bfr[4][4];
            uint32_t ak = ((uint32_t)(kk * 32) + a_khoff) ^ swzmask;
            uint32_t bk = ((uint32_t)(kk * 32) + b_khoff) ^ swzmask;
            ldmat4(a, sb + (uint32_t)(s * 8192) + a_rowbase + ak);
#pragma unroll
            for (int q = 0; q < 4; q++)
                ldmat4(bfr[q], sb + 24576u + (uint32_t)(s * 8192)
                               + b_rowbase + (uint32_t)(q * 2048) + bk);
#pragma unroll
            for (int j = 0; j < 8; j++)
                mma16(acc[j], a, &bfr[j >> 1][(j & 1) * 2]);
        }
    }

    // store: rows b = wid*16 + lgrp (+8), cols o = j*8 + lane4*2
    int brow = wid * 16 + lgrp;
#pragma unroll
    for (int j = 0; j < 8; j++) {
        int o = j * 8 + lane4 * 2;
        float b0 = biass[o], b1 = biass[o + 1];
        *(float2*)&out[((size_t)brow * NN + n) * CC + o] =
            make_float2(acc[j][0] + b0, acc[j][1] + b1);
        *(float2*)&out[((size_t)(brow + 8) * NN + n) * CC + o] =
            make_float2(acc[j][2] + b0, acc[j][3] + b1);
    }
}

// ---------------- launch ----------------------------------------------------
#define GEMM_SMEM 98304

extern "C" void kernel_launch(void* const* d_in, const int* in_sizes, int n_in,
                              void* d_out, int out_size)
{
    const float* x  = (const float*)d_in[0];
    const float* E  = (const float*)d_in[1];
    const float* Wp = (const float*)d_in[2];
    const float* bp = (const float*)d_in[3];
    float* out = (float*)d_out;

    __half *pAh, *pxTTh, *pXg1h, *pXg1T, *pXg2ph;
    cudaGetSymbolAddress((void**)&pAh,    g_Ah);
    cudaGetSymbolAddress((void**)&pxTTh,  g_xTTh);
    cudaGetSymbolAddress((void**)&pXg1h,  g_Xg1h);
    cudaGetSymbolAddress((void**)&pXg1T,  g_Xg1T);
    cudaGetSymbolAddress((void**)&pXg2ph, g_Xg2ph);

    static bool init_done = false;
    static cudaStream_t s1, s2;
    static cudaEvent_t e0, e1, e2;
    if (!init_done) {
        cudaFuncSetAttribute(gemm_mma, cudaFuncAttributeMaxDynamicSharedMemorySize, GEMM_SMEM);
        cudaFuncSetAttribute(final_tc, cudaFuncAttributeMaxDynamicSharedMemorySize, FT_SMEM);
        cudaStreamCreateWithFlags(&s1, cudaStreamNonBlocking);
        cudaStreamCreateWithFlags(&s2, cudaStreamNonBlocking);
        cudaEventCreateWithFlags(&e0, cudaEventDisableTiming);
        cudaEventCreateWithFlags(&e1, cudaEventDisableTiming);
        cudaEventCreateWithFlags(&e2, cudaEventDisableTiming);
        init_done = true;
    }

    // fork side streams from the capture-origin (default) stream
    cudaEventRecord(e0, 0);
    cudaStreamWaitEvent(s1, e0, 0);
    cudaStreamWaitEvent(s2, e0, 0);

    // s1: x transposes (fp16)         — xTTh for GEMM1, xh for final_tc
    transpose_x_kernel<<<dim3(64, 2, 64), dim3(32, 8), 0, s1>>>(x);
    // s2: weight prep + per-node weights (fp16, transposed, W0-W2 folded)
    prepW_kernel<<<480, 256, 0, s2>>>(Wp);
    weights_kernel<<<(NN * 1536) / 256, 256, 0, s2>>>(E);
    cudaEventRecord(e2, s2);
    // main: adjacency (fp16)          — needed by both GEMMs
    supports_kernel<<<NN, 256>>>(E);

    // join s1 before GEMM1
    cudaEventRecord(e1, s1);
    cudaStreamWaitEvent(0, e1, 0);

    // GEMM1: Xg1h = fp16(A @ xT)  (+ fused fp16 transposed copy Xg1T)
    gemm_mma<<<dim3(BC / 128, NN / 128), 256, GEMM_SMEM>>>(pAh, pxTTh, pXg1h, BC, 1.0f, pXg1T);
    // GEMM2: Xg2ph = fp16(2 A @ Xg1)
    gemm_mma<<<dim3(BC / 128, NN / 128), 256, GEMM_SMEM>>>(pAh, pXg1T, pXg2ph, BC, 2.0f, nullptr);

    // join s2 (weights), then fused tensor-core final
    cudaStreamWaitEvent(0, e2, 0);
    final_tc<<<NN, 128, FT_SMEM>>>(E, bp, out);
}

// round 11
// speedup vs baseline: 1.3697x; 1.0472x over previous
#include <cuda_runtime.h>
#include <cuda_fp16.h>
#include <cstdint>

// Problem constants
#define NN   2048
#define BB   64
#define CC   64
#define ED   10
#define BC   4096
#define KCH  3

// ---------------- scratch ------------------------------------------------------
__device__ __half g_Eth  [(size_t)ED * NN];   // E^T fp16 [d][m] (coalesced supports reads)
__device__ __half g_Ah   [(size_t)NN * NN];   // softmax(relu(E E^T)), fp16
__device__ __half g_xTTh [(size_t)BC * NN];   // xTT[b*64+c][n], fp16 (GEMM1 B operand)
__device__ __half g_xh   [(size_t)NN * BC];   // x as [n][b*64+c], fp16 (final_tc seg0)
__device__ __half g_Xg1h [(size_t)NN * BC];   // A @ xT, fp16 [n][bc]
__device__ __half g_Xg1T [(size_t)BC * NN];   // Xg1^T fp16 (GEMM2 B operand)
__device__ __half g_Xg2ph[(size_t)NN * BC];   // 2 A @ Xg1, fp16 [n][bc]
__device__ __half g_Wph  [(size_t)ED * KCH * CC * CC]; // Wp [d][k][o][i], slot0 folded
__device__ __half g_WhT  [(size_t)NN * KCH * CC * CC]; // per-node W^T [n][k][o][i]

// ---------------- helpers ------------------------------------------------
__device__ __forceinline__ uint32_t smem_u32(const void* p) {
    uint32_t a;
    asm("{ .reg .u64 t; cvta.to.shared.u64 t, %1; cvt.u32.u64 %0, t; }" : "=r"(a) : "l"(p));
    return a;
}
__device__ __forceinline__ void cp16(uint32_t dst, const void* src) {
    asm volatile("cp.async.cg.shared.global [%0], [%1], 16;" :: "r"(dst), "l"(src) : "memory");
}
__device__ __forceinline__ void mma16(float* d, const uint32_t* a, const uint32_t* b) {
    asm volatile("mma.sync.aligned.m16n8k16.row.col.f32.f16.f16.f32 "
        "{%0,%1,%2,%3}, {%4,%5,%6,%7}, {%8,%9}, {%0,%1,%2,%3};"
        : "+f"(d[0]), "+f"(d[1]), "+f"(d[2]), "+f"(d[3])
        : "r"(a[0]), "r"(a[1]), "r"(a[2]), "r"(a[3]), "r"(b[0]), "r"(b[1]));
}
__device__ __forceinline__ void ldmat4(uint32_t* r, uint32_t addr) {
    asm volatile("ldmatrix.sync.aligned.m8n8.x4.shared.b16 {%0,%1,%2,%3}, [%4];"
        : "=r"(r[0]), "=r"(r[1]), "=r"(r[2]), "=r"(r[3]) : "r"(addr));
}

// ---------------- fp16 mma.sync GEMM: Ch = fp16(alpha * Aop @ Bop^T) ---------
// CTA tile 128x128, warp tile 64x32, K-chunk 64, 3-stage cp.async pipeline.
// by0: M-block offset (for M-split launches).
// If Ct != null, also writes fp16 transposed tile to Ct (ld = NN).
__global__ __launch_bounds__(256, 2)
void gemm_mma(const __half* __restrict__ Aop, const __half* __restrict__ Bop,
              __half* __restrict__ Ch, int ldcN, float alpha,
              __half* __restrict__ Ct, int by0)
{
    extern __shared__ char smem[];
    uint32_t sbase = smem_u32(smem);

    int tid = threadIdx.x, wid = tid >> 5, lid = tid & 31;
    int m0 = (blockIdx.y + by0) * 128, n0 = blockIdx.x * 128;

    int ldr = tid >> 3, ldc8 = tid & 7;
    uint32_t swz_ld = (uint32_t)(ldr * 128 + ((ldc8 * 16) ^ ((ldr & 7) * 16)));
    const __half* ga = Aop + (size_t)(m0 + ldr) * NN + ldc8 * 8;
    const __half* gb = Bop + (size_t)(n0 + ldr) * NN + ldc8 * 8;

#define LOAD_CHUNK(kc, buf) do { \
    int _k0 = (kc) * 64; \
    uint32_t _as = sbase + (uint32_t)(buf) * 32768u + swz_ld; \
    uint32_t _bs = _as + 16384u; \
    _Pragma("unroll") for (int i = 0; i < 4; i++) { \
        cp16(_as + (uint32_t)i * 4096u, ga + (size_t)i * 32 * NN + _k0); \
        cp16(_bs + (uint32_t)i * 4096u, gb + (size_t)i * 32 * NN + _k0); \
    } \
    asm volatile("cp.async.commit_group;" ::: "memory"); \
} while (0)

    int wm = wid & 1, wn = wid >> 1;
    int lane4 = lid & 3, lgrp = lid >> 2;
    int t7 = lid & 7;
    uint32_t swzmask = (uint32_t)(t7 * 16);

    uint32_t a_rowbase = (uint32_t)((wm * 64 + t7 + (((lid >> 3) & 1) << 3)) * 128);
    uint32_t a_khoff   = (uint32_t)(((lid >> 4) & 1) * 16);
    uint32_t b_rowbase = (uint32_t)((wn * 32 + t7 + (((lid >> 4) & 1) << 3)) * 128);
    uint32_t b_khoff   = (uint32_t)(((lid >> 3) & 1) * 16);

    float acc[4][4][4];
#pragma unroll
    for (int mt = 0; mt < 4; mt++)
#pragma unroll
        for (int nt = 0; nt < 4; nt++)
#pragma unroll
            for (int c = 0; c < 4; c++) acc[mt][nt][c] = 0.f;

    LOAD_CHUNK(0, 0);
    LOAD_CHUNK(1, 1);

    int buf = 0, nbuf = 2;
    for (int kc = 0; kc < 32; kc++) {
        asm volatile("cp.async.wait_group 1;" ::: "memory");
        __syncthreads();

        if (kc + 2 < 32) LOAD_CHUNK(kc + 2, nbuf);
        else asm volatile("cp.async.commit_group;" ::: "memory");

        uint32_t ab = sbase + (uint32_t)buf * 32768u;
        uint32_t bb = ab + 16384u;
#pragma unroll
        for (int kk = 0; kk < 4; kk++) {
            uint32_t a[4][4], bfr[2][4];
            uint32_t a_k = ((uint32_t)(kk * 32) + a_khoff) ^ swzmask;
            uint32_t b_k = ((uint32_t)(kk * 32) + b_khoff) ^ swzmask;
#pragma unroll
            for (int mt = 0; mt < 4; mt++)
                ldmat4(a[mt], ab + a_rowbase + (uint32_t)(mt * 2048) + a_k);
#pragma unroll
            for (int np = 0; np < 2; np++)
                ldmat4(bfr[np], bb + b_rowbase + (uint32_t)(np * 2048) + b_k);
#pragma unroll
            for (int mt = 0; mt < 4; mt++)
#pragma unroll
                for (int nt = 0; nt < 4; nt++)
                    mma16(acc[mt][nt], a[mt], &bfr[nt >> 1][(nt & 1) * 2]);
        }
        int t = buf; buf = (buf == 2) ? 0 : buf + 1; nbuf = t;
    }
#undef LOAD_CHUNK

    // ---- epilogue ----
    __syncthreads();
    float* st = (float*)smem;  // 128 x 128 staging, stride 129

    int row0 = m0 + wm * 64;
    int col0 = n0 + wn * 32 + lane4 * 2;
    int lr0  = wm * 64;
    int lc0  = wn * 32 + lane4 * 2;
#pragma unroll
    for (int mt = 0; mt < 4; mt++) {
#pragma unroll
        for (int nt = 0; nt < 4; nt++) {
            int r = row0 + mt * 16 + lgrp;
            int c = col0 + nt * 8;
            float v0 = alpha * acc[mt][nt][0];
            float v1 = alpha * acc[mt][nt][1];
            float v2 = alpha * acc[mt][nt][2];
            float v3 = alpha * acc[mt][nt][3];
            *(__half2*)&Ch[(size_t)r * ldcN + c]       = __floats2half2_rn(v0, v1);
            *(__half2*)&Ch[(size_t)(r + 8) * ldcN + c] = __floats2half2_rn(v2, v3);
            if (Ct) {
                int lr = lr0 + mt * 16 + lgrp;
                int lc = lc0 + nt * 8;
                st[lr * 129 + lc]           = v0;
                st[lr * 129 + lc + 1]       = v1;
                st[(lr + 8) * 129 + lc]     = v2;
                st[(lr + 8) * 129 + lc + 1] = v3;
            }
        }
    }
    if (Ct) {
        __syncthreads();
        for (int i = tid; i < 16384; i += 256) {
            int c = i >> 7, r = i & 127;
            Ct[(size_t)(n0 + c) * NN + m0 + r] = __float2half_rn(st[r * 129 + c]);
        }
    }
}

// ---------------- prepE: Eth[d][m] = fp16(E[m][d]) ---------------------------
__global__ __launch_bounds__(256) void prepE_kernel(const float* __restrict__ E)
{
    int t = blockIdx.x * 256 + threadIdx.x;   // 20480 elements
    if (t < ED * NN) {
        int m = t & (NN - 1);
        int d = t >> 11;
        g_Eth[(size_t)d * NN + m] = __float2half_rn(E[m * ED + d]);
    }
}

// ---------------- A = softmax(relu(E E^T)), coalesced reads, __expf ----------
__global__ __launch_bounds__(256) void supports_kernel(const float* __restrict__ E)
{
    int n = blockIdx.x, tid = threadIdx.x;
    float en[ED];
#pragma unroll
    for (int d = 0; d < ED; d++) en[d] = E[n * ED + d];

    float v[8], mx = 0.0f;
#pragma unroll
    for (int j = 0; j < 8; j++) {
        int m = j * 256 + tid;
        float dot = 0.f;
#pragma unroll
        for (int d = 0; d < ED; d++)
            dot += en[d] * __half2float(g_Eth[(size_t)d * NN + m]);   // coalesced in m
        v[j] = fmaxf(dot, 0.f);
        mx = fmaxf(mx, v[j]);
    }
    __shared__ float red[256];
    red[tid] = mx; __syncthreads();
    for (int s = 128; s > 0; s >>= 1) {
        if (tid < s) red[tid] = fmaxf(red[tid], red[tid + s]);
        __syncthreads();
    }
    mx = red[0]; __syncthreads();
    float sum = 0.f;
#pragma unroll
    for (int j = 0; j < 8; j++) { v[j] = __expf(v[j] - mx); sum += v[j]; }
    red[tid] = sum; __syncthreads();
    for (int s = 128; s > 0; s >>= 1) {
        if (tid < s) red[tid] += red[tid + s];
        __syncthreads();
    }
    float inv = 1.0f / red[0];
#pragma unroll
    for (int j = 0; j < 8; j++)
        g_Ah[(size_t)n * NN + j * 256 + tid] = __float2half_rn(v[j] * inv);
}

// ---------------- x transposes: xTTh [bc][n] + xh [n][bc], both fp16 ---------
__global__ __launch_bounds__(256) void transpose_x_kernel(const float* __restrict__ x)
{
    __shared__ float t[32][33];
    int tx = threadIdx.x, ty = threadIdx.y;
    int b = blockIdx.z;
    int n0 = blockIdx.x * 32, c0 = blockIdx.y * 32;
    const float* S = x + (size_t)b * NN * CC;
#pragma unroll
    for (int i = 0; i < 32; i += 8) {
        float v = S[(size_t)(n0 + ty + i) * CC + c0 + tx];
        t[ty + i][tx] = v;
        g_xh[(size_t)(n0 + ty + i) * BC + b * CC + c0 + tx] = __float2half_rn(v);
    }
    __syncthreads();
    __half* D = g_xTTh + (size_t)b * CC * NN;
#pragma unroll
    for (int i = 0; i < 32; i += 8)
        D[(size_t)(c0 + ty + i) * NN + n0 + tx] = __float2half_rn(t[tx][ty + i]);
}

// ---------------- prepW: Wph[d][k][o][i] = fp16(Wp[d][k][i][o] - (k==0)*Wp[d][2][i][o])
__global__ __launch_bounds__(256) void prepW_kernel(const float* __restrict__ Wp)
{
    int t = blockIdx.x * 256 + threadIdx.x;     // 122880 elements
    int i  = t & 63;
    int o  = (t >> 6) & 63;
    int kd = t >> 12;                            // d*3 + k
    int k  = kd % 3, d = kd / 3;
    float v = Wp[((size_t)kd * 64 + i) * 64 + o];
    if (k == 0) v -= Wp[((size_t)(d * 3 + 2) * 64 + i) * 64 + o];
    g_Wph[t] = __float2half_rn(v);
}

// ---------------- weights: WhT[n][k][o][i] = sum_d E[n,d] Wph[d][k][o][i] ----
__global__ __launch_bounds__(256) void weights_kernel(const float* __restrict__ E)
{
    size_t t = (size_t)blockIdx.x * 256 + threadIdx.x;  // 2048*1536
    int j8 = (int)(t % 1536);
    int n  = (int)(t / 1536);

    float acc[8];
#pragma unroll
    for (int q = 0; q < 8; q++) acc[q] = 0.f;

#pragma unroll
    for (int d = 0; d < ED; d++) {
        float e = __ldg(&E[n * ED + d]);
        uint4 w = *(const uint4*)&g_Wph[(size_t)d * 12288 + (size_t)j8 * 8];
        const __half2* h = (const __half2*)&w;
#pragma unroll
        for (int q = 0; q < 4; q++) {
            float2 f = __half22float2(h[q]);
            acc[q * 2]     += e * f.x;
            acc[q * 2 + 1] += e * f.y;
        }
    }
    uint4 outw;
    __half2* ho = (__half2*)&outw;
#pragma unroll
    for (int q = 0; q < 4; q++)
        ho[q] = __floats2half2_rn(acc[q * 2], acc[q * 2 + 1]);
    *(uint4*)&g_WhT[(size_t)n * 12288 + (size_t)j8 * 8] = outw;
}

// ---------------- final_tc: out[:,n,:] = [x|Xg1|Xg2p] @ WhT_n + bias ---------
#define FT_SMEM (49152 + 256)
__global__ __launch_bounds__(128)
void final_tc(const float* __restrict__ E, const float* __restrict__ bp,
              float* __restrict__ out, int n0off)
{
    extern __shared__ char sm[];
    uint32_t sb = smem_u32(sm);
    float* biass = (float*)(sm + 49152);
    int n = blockIdx.x + n0off, tid = threadIdx.x, wid = tid >> 5, lid = tid & 31;

    if (tid < 64) {
        float b = 0.f;
#pragma unroll
        for (int d = 0; d < ED; d++) b += __ldg(&E[n * ED + d]) * __ldg(&bp[d * CC + tid]);
        biass[tid] = b;
    }

    const __half* srcs[3] = { g_xh   + (size_t)n * BC,
                              g_Xg1h + (size_t)n * BC,
                              g_Xg2ph+ (size_t)n * BC };
#pragma unroll
    for (int s = 0; s < 3; s++) {
        const char* g = (const char*)srcs[s];
        for (int ch = tid; ch < 512; ch += 128) {
            int r = ch >> 3, c16 = ch & 7;
            uint32_t dst = sb + (uint32_t)(s * 8192)
                         + (uint32_t)(r * 128 + ((c16 * 16) ^ ((r & 7) * 16)));
            cp16(dst, g + r * 128 + c16 * 16);
        }
    }
    {
        const char* g = (const char*)(g_WhT + (size_t)n * 12288);
        for (int ch = tid; ch < 1536; ch += 128) {
            int r = ch >> 3, c16 = ch & 7;
            uint32_t dst = sb + 24576u
                         + (uint32_t)(r * 128 + ((c16 * 16) ^ ((r & 7) * 16)));
            cp16(dst, g + r * 128 + c16 * 16);
        }
    }
    asm volatile("cp.async.commit_group;" ::: "memory");
    asm volatile("cp.async.wait_group 0;" ::: "memory");
    __syncthreads();

    int t7 = lid & 7, lane4 = lid & 3, lgrp = lid >> 2;
    uint32_t swzmask = (uint32_t)(t7 * 16);
    uint32_t a_rowbase = (uint32_t)((wid * 16 + t7 + (((lid >> 3) & 1) << 3)) * 128);
    uint32_t a_khoff   = (uint32_t)(((lid >> 4) & 1) * 16);
    uint32_t b_rowbase = (uint32_t)((t7 + (((lid >> 4) & 1) << 3)) * 128);
    uint32_t b_khoff   = (uint32_t)(((lid >> 3) & 1) * 16);

    float acc[8][4];
#pragma unroll
    for (int j = 0; j < 8; j++)
#pragma unroll
        for (int c = 0; c < 4; c++) acc[j][c] = 0.f;

#pragma unroll
    for (int s = 0; s < 3; s++) {
#pragma unroll
        for (int kk = 0; kk < 4; kk++) {
            uint32_t a[4], bfr[4][4];
            uint32_t ak = ((uint32_t)(kk * 32) + a_khoff) ^ swzmask;
            uint32_t bk = ((uint32_t)(kk * 32) + b_khoff) ^ swzmask;
            ldmat4(a, sb + (uint32_t)(s * 8192) + a_rowbase + ak);
#pragma unroll
            for (int q = 0; q < 4; q++)
                ldmat4(bfr[q], sb + 24576u + (uint32_t)(s * 8192)
                               + b_rowbase + (uint32_t)(q * 2048) + bk);
#pragma unroll
            for (int j = 0; j < 8; j++)
                mma16(acc[j], a, &bfr[j >> 1][(j & 1) * 2]);
        }
    }

    int brow = wid * 16 + lgrp;
#pragma unroll
    for (int j = 0; j < 8; j++) {
        int o = j * 8 + lane4 * 2;
        float b0 = biass[o], b1 = biass[o + 1];
        *(float2*)&out[((size_t)brow * NN + n) * CC + o] =
            make_float2(acc[j][0] + b0, acc[j][1] + b1);
        *(float2*)&out[((size_t)(brow + 8) * NN + n) * CC + o] =
            make_float2(acc[j][2] + b0, acc[j][3] + b1);
    }
}

// ---------------- launch ----------------------------------------------------
#define GEMM_SMEM 98304

extern "C" void kernel_launch(void* const* d_in, const int* in_sizes, int n_in,
                              void* d_out, int out_size)
{
    const float* x  = (const float*)d_in[0];
    const float* E  = (const float*)d_in[1];
    const float* Wp = (const float*)d_in[2];
    const float* bp = (const float*)d_in[3];
    float* out = (float*)d_out;

    __half *pAh, *pxTTh, *pXg1h, *pXg1T, *pXg2ph;
    cudaGetSymbolAddress((void**)&pAh,    g_Ah);
    cudaGetSymbolAddress((void**)&pxTTh,  g_xTTh);
    cudaGetSymbolAddress((void**)&pXg1h,  g_Xg1h);
    cudaGetSymbolAddress((void**)&pXg1T,  g_Xg1T);
    cudaGetSymbolAddress((void**)&pXg2ph, g_Xg2ph);

    static bool init_done = false;
    static cudaStream_t s1, s2;
    static cudaEvent_t e0, e1, e2, eG2a, eFa;
    if (!init_done) {
        cudaFuncSetAttribute(gemm_mma, cudaFuncAttributeMaxDynamicSharedMemorySize, GEMM_SMEM);
        cudaFuncSetAttribute(final_tc, cudaFuncAttributeMaxDynamicSharedMemorySize, FT_SMEM);
        cudaStreamCreateWithFlags(&s1, cudaStreamNonBlocking);
        cudaStreamCreateWithFlags(&s2, cudaStreamNonBlocking);
        cudaEventCreateWithFlags(&e0,   cudaEventDisableTiming);
        cudaEventCreateWithFlags(&e1,   cudaEventDisableTiming);
        cudaEventCreateWithFlags(&e2,   cudaEventDisableTiming);
        cudaEventCreateWithFlags(&eG2a, cudaEventDisableTiming);
        cudaEventCreateWithFlags(&eFa,  cudaEventDisableTiming);
        init_done = true;
    }

    // fork side streams from the capture-origin (default) stream
    cudaEventRecord(e0, 0);
    cudaStreamWaitEvent(s1, e0, 0);
    cudaStreamWaitEvent(s2, e0, 0);

    // s1: x transposes (fp16)
    transpose_x_kernel<<<dim3(64, 2, 64), dim3(32, 8), 0, s1>>>(x);
    // s2: weight prep + per-node weights
    prepW_kernel<<<480, 256, 0, s2>>>(Wp);
    weights_kernel<<<(NN * 1536) / 256, 256, 0, s2>>>(E);
    cudaEventRecord(e2, s2);
    // main: E transpose, then adjacency (coalesced + __expf)
    prepE_kernel<<<80, 256>>>(E);
    supports_kernel<<<NN, 256>>>(E);

    // join s1 before GEMM1
    cudaEventRecord(e1, s1);
    cudaStreamWaitEvent(0, e1, 0);

    // GEMM1: Xg1h = fp16(A @ xT)  (+ fused fp16 transposed copy Xg1T)
    gemm_mma<<<dim3(BC / 128, NN / 128), 256, GEMM_SMEM>>>(pAh, pxTTh, pXg1h, BC, 1.0f, pXg1T, 0);

    // GEMM2a: Xg2ph rows 0..1023 (M blocks 0..7)
    gemm_mma<<<dim3(BC / 128, 8), 256, GEMM_SMEM>>>(pAh, pXg1T, pXg2ph, BC, 2.0f, nullptr, 0);
    cudaEventRecord(eG2a, 0);

    // s2: final_tc for nodes 0..1023, overlapping GEMM2b
    cudaStreamWaitEvent(s2, eG2a, 0);   // implies GEMM1 + transpose_x done too
    final_tc<<<1024, 128, FT_SMEM, s2>>>(E, bp, out, 0);
    cudaEventRecord(eFa, s2);

    // main: GEMM2b rows 1024..2047
    gemm_mma<<<dim3(BC / 128, 8), 256, GEMM_SMEM>>>(pAh, pXg1T, pXg2ph, BC, 2.0f, nullptr, 8);

    // main: final_tc for nodes 1024..2047 (weights e2 ordered via s2 events? join explicitly)
    cudaStreamWaitEvent(0, e2, 0);
    final_tc<<<1024, 128, FT_SMEM>>>(E, bp, out, 1024);

    // join s2's final half back to the capture-origin stream
    cudaStreamWaitEvent(0, eFa, 0);
}